// round 10
// baseline (speedup 1.0000x reference)
#include <cuda_runtime.h>
#include <cuda_bf16.h>
#include <cstdint>

// ---------------------------------------------------------------------------
// 3-layer GraphSAGE (mean aggregation), fp32-grade via bf16 hi/lo pairs.
//   activations stored as TWO bf16 arrays (hi, lo); value = hi + lo.
//   aggregation: CSR segment-mean gather, C/128 warps per node
//   GEMM: mma.sync m16n8k16 bf16, 3 products, cp.async 2-stage pipeline,
//         ldmatrix.x4 fragment loads.
// N = 100000, E = 1600000, dims 128 -> 256 -> 256 -> 256.
// ---------------------------------------------------------------------------

#define NN 100000
#define NE 1600000
#define CMAX 256

// ---------------- split activation buffers (hi / lo bf16) ------------------
__device__ __align__(16) __nv_bfloat16 g_xh  [(size_t)NN * 128];
__device__ __align__(16) __nv_bfloat16 g_xl  [(size_t)NN * 128];
__device__ __align__(16) __nv_bfloat16 g_aggh[(size_t)NN * CMAX];
__device__ __align__(16) __nv_bfloat16 g_aggl[(size_t)NN * CMAX];
__device__ __align__(16) __nv_bfloat16 g_h0h [(size_t)NN * CMAX];
__device__ __align__(16) __nv_bfloat16 g_h0l [(size_t)NN * CMAX];
__device__ __align__(16) __nv_bfloat16 g_h1h [(size_t)NN * CMAX];
__device__ __align__(16) __nv_bfloat16 g_h1l [(size_t)NN * CMAX];

// split transposed weights [N=256, K] (K contiguous)
#define WBUF_TOTAL (2 * 128 * 256 + 4 * 256 * 256)
__device__ __align__(16) __nv_bfloat16 g_Wh[WBUF_TOTAL];
__device__ __align__(16) __nv_bfloat16 g_Wl[WBUF_TOTAL];

// CSR build
#define SCAN_B 512
#define NB1 ((NN + SCAN_B - 1) / SCAN_B)
__device__ int g_cnt[NN];
__device__ int g_pos[NN];
__device__ int g_rowptr[NN];
__device__ int g_srcs[NE];
__device__ int g_scan[NN];
__device__ int g_part[NB1];
__device__ int g_partscan[NB1];

// ---------------------------------------------------------------------------
// helpers
// ---------------------------------------------------------------------------
__device__ __forceinline__ void split_bf16(float v, __nv_bfloat16& h, __nv_bfloat16& l) {
    h = __float2bfloat16_rn(v);
    l = __float2bfloat16_rn(v - __bfloat162float(h));
}
__device__ __forceinline__ uint32_t pack2(__nv_bfloat16 a, __nv_bfloat16 b) {
    __nv_bfloat162 p = __halves2bfloat162(a, b);
    return *reinterpret_cast<uint32_t*>(&p);
}
__device__ __forceinline__ void acc_u32pair(float& a0, float& a1, uint32_t u) {
    a0 += __uint_as_float(u << 16);
    a1 += __uint_as_float(u & 0xFFFF0000u);
}
__device__ __forceinline__ void cpa16(uint32_t saddr, const void* g, int sz) {
    asm volatile("cp.async.ca.shared.global [%0], [%1], 16, %2;"
                 :: "r"(saddr), "l"(g), "r"(sz) : "memory");
}
__device__ __forceinline__ uint32_t smem_u32p(const void* p) {
    uint32_t a;
    asm("{ .reg .u64 t; cvta.to.shared.u64 t, %1; cvt.u32.u64 %0, t; }" : "=r"(a) : "l"(p));
    return a;
}
__device__ __forceinline__ void ldsm4(uint32_t* r, uint32_t saddr) {
    asm volatile("ldmatrix.sync.aligned.m8n8.x4.shared.b16 {%0,%1,%2,%3}, [%4];"
                 : "=r"(r[0]), "=r"(r[1]), "=r"(r[2]), "=r"(r[3]) : "r"(saddr));
}
__device__ __forceinline__ void mma2(float* c, const uint32_t* a, uint32_t b0, uint32_t b1) {
    asm volatile(
        "mma.sync.aligned.m16n8k16.row.col.f32.bf16.bf16.f32 "
        "{%0,%1,%2,%3}, {%4,%5,%6,%7}, {%8,%9}, {%0,%1,%2,%3};"
        : "+f"(c[0]), "+f"(c[1]), "+f"(c[2]), "+f"(c[3])
        : "r"(a[0]), "r"(a[1]), "r"(a[2]), "r"(a[3]), "r"(b0), "r"(b1));
}

// ---------------------------------------------------------------------------
// CSR build kernels
// ---------------------------------------------------------------------------
__global__ void k_zero_cnt() {
    int i = blockIdx.x * blockDim.x + threadIdx.x;
    if (i < NN) { g_cnt[i] = 0; g_pos[i] = 0; }
}
__global__ void k_hist(const int* __restrict__ dst) {
    int i = blockIdx.x * blockDim.x + threadIdx.x;
    if (i < NE) atomicAdd(&g_cnt[dst[i]], 1);
}
__global__ void k_scan1() {
    __shared__ int s[SCAN_B];
    int t = threadIdx.x;
    int idx = blockIdx.x * SCAN_B + t;
    int v = (idx < NN) ? g_cnt[idx] : 0;
    s[t] = v;
    __syncthreads();
#pragma unroll
    for (int off = 1; off < SCAN_B; off <<= 1) {
        int tmp = (t >= off) ? s[t - off] : 0;
        __syncthreads();
        s[t] += tmp;
        __syncthreads();
    }
    if (idx < NN) g_scan[idx] = s[t];
    if (t == SCAN_B - 1) g_part[blockIdx.x] = s[t];
}
__global__ void k_scan2() {
    __shared__ int s[256];
    int t = threadIdx.x;
    int v = (t < NB1) ? g_part[t] : 0;
    s[t] = v;
    __syncthreads();
#pragma unroll
    for (int off = 1; off < 256; off <<= 1) {
        int tmp = (t >= off) ? s[t - off] : 0;
        __syncthreads();
        s[t] += tmp;
        __syncthreads();
    }
    if (t < NB1) g_partscan[t] = s[t];
}
__global__ void k_scan3() {
    int idx = blockIdx.x * blockDim.x + threadIdx.x;
    if (idx < NN) {
        int b = idx / SCAN_B;
        int boff = (b > 0) ? g_partscan[b - 1] : 0;
        g_rowptr[idx] = g_scan[idx] - g_cnt[idx] + boff;
    }
}
__global__ void k_place(const int* __restrict__ src, const int* __restrict__ dst) {
    int i = blockIdx.x * blockDim.x + threadIdx.x;
    if (i < NE) {
        int d = dst[i];
        int pos = g_rowptr[d] + atomicAdd(&g_pos[d], 1);
        g_srcs[pos] = src[i];
    }
}

// ---------------------------------------------------------------------------
// prep: split x; split+transpose all 6 weights in ONE kernel
// segments: l0 [0,32768) K=128 | r0 [32768,65536) K=128
//           l1 [65536,131072) | r1 [131072,196608) | l2 [196608,262144) | r2 [262144,327680)
// ---------------------------------------------------------------------------
__global__ void k_prep_x(const float* __restrict__ x) {
    int i = blockIdx.x * blockDim.x + threadIdx.x;
    if (i >= NN * 64) return;
    float2 v = reinterpret_cast<const float2*>(x)[i];
    __nv_bfloat16 h0, l0, h1, l1;
    split_bf16(v.x, h0, l0);
    split_bf16(v.y, h1, l1);
    reinterpret_cast<uint32_t*>(g_xh)[i] = pack2(h0, h1);
    reinterpret_cast<uint32_t*>(g_xl)[i] = pack2(l0, l1);
}
__global__ void k_prep_w_all(const float* __restrict__ Wl0, const float* __restrict__ Wr0,
                             const float* __restrict__ Wl1, const float* __restrict__ Wr1,
                             const float* __restrict__ Wl2, const float* __restrict__ Wr2) {
    int i = blockIdx.x * blockDim.x + threadIdx.x;
    if (i >= 327680) return;
    const float* W;
    int base, K, li;
    if (i < 65536) {
        K = 128;
        if (i < 32768) { W = Wl0; base = 0; li = i; }
        else           { W = Wr0; base = 32768; li = i - 32768; }
    } else {
        K = 256;
        int j = i - 65536;
        int seg = j >> 16;          // 0..3
        li = j & 65535;
        base = 65536 + (seg << 16);
        W = (seg == 0) ? Wl1 : (seg == 1) ? Wr1 : (seg == 2) ? Wl2 : Wr2;
    }
    int k = (K == 128) ? (li >> 8) : (li >> 8);
    int n = li & 255;
    __nv_bfloat16 h, l;
    split_bf16(W[li], h, l);
    g_Wh[base + n * K + k] = h;
    g_Wl[base + n * K + k] = l;
}

// ---------------------------------------------------------------------------
// aggregation: segment-mean gather over split hi/lo arrays.
// C/128 warps per node; each lane covers 4 channels (uint2 hi + uint2 lo).
// ---------------------------------------------------------------------------
template <int C>   // 128 or 256
__global__ void k_aggregate(int xsel) {
    const __nv_bfloat16 *xh, *xl;
    if (xsel == 0)      { xh = g_xh;  xl = g_xl;  }
    else if (xsel == 1) { xh = g_h0h; xl = g_h0l; }
    else                { xh = g_h1h; xl = g_h1l; }

    constexpr int WPN = C / 128;   // warps per node
    int gw = (blockIdx.x * blockDim.x + threadIdx.x) >> 5;
    int lane = threadIdx.x & 31;
    int node = gw / WPN;
    int chunk = gw - node * WPN;
    if (node >= NN) return;

    int beg = g_rowptr[node];
    int len = g_cnt[node];
    int end = beg + len;

    const int u0 = chunk * 64 + lane * 2;   // u32 offset within row (row = C/2 u32)

    float a0 = 0.f, a1 = 0.f, a2 = 0.f, a3 = 0.f;

    auto gather_one = [&](int s) {
        const uint32_t* rh = reinterpret_cast<const uint32_t*>(xh + (size_t)s * C);
        const uint32_t* rl = reinterpret_cast<const uint32_t*>(xl + (size_t)s * C);
        uint2 vh = *reinterpret_cast<const uint2*>(rh + u0);
        uint2 vl = *reinterpret_cast<const uint2*>(rl + u0);
        acc_u32pair(a0, a1, vh.x); acc_u32pair(a0, a1, vl.x);
        acc_u32pair(a2, a3, vh.y); acc_u32pair(a2, a3, vl.y);
    };

    int j = beg;
    for (; j + 4 <= end; j += 4) {
        int s0 = __ldg(&g_srcs[j + 0]);
        int s1 = __ldg(&g_srcs[j + 1]);
        int s2 = __ldg(&g_srcs[j + 2]);
        int s3 = __ldg(&g_srcs[j + 3]);
        gather_one(s0); gather_one(s1); gather_one(s2); gather_one(s3);
    }
    for (; j < end; ++j) gather_one(__ldg(&g_srcs[j]));

    float inv = 1.0f / fmaxf((float)len, 1.0f);
    __nv_bfloat16 h0, l0, h1, l1, h2, l2, h3, l3;
    split_bf16(a0 * inv, h0, l0);
    split_bf16(a1 * inv, h1, l1);
    split_bf16(a2 * inv, h2, l2);
    split_bf16(a3 * inv, h3, l3);
    uint32_t* wh = reinterpret_cast<uint32_t*>(g_aggh + (size_t)node * C);
    uint32_t* wl = reinterpret_cast<uint32_t*>(g_aggl + (size_t)node * C);
    *reinterpret_cast<uint2*>(wh + u0) = make_uint2(pack2(h0, h1), pack2(h2, h3));
    *reinterpret_cast<uint2*>(wl + u0) = make_uint2(pack2(l0, l1), pack2(l2, l3));
}

// ---------------------------------------------------------------------------
// fused dual-GEMM: C = agg@W_l + A2@W_r + bias (+relu)
//   split hi/lo smem tiles staged by cp.async (2-stage), ldmatrix.x4
//   fragment loads, 3 mma products.
// ---------------------------------------------------------------------------
#define BM 128
#define BN 128
#define SBF 40                                  // bf16 per smem row -> 80 B
#define TILE_BF (128 * SBF)                     // 5120 bf16 per tile
#define STG_BF (4 * TILE_BF)                    // Ah, Al, Bh, Bl
#define SMEM_BYTES (2 * STG_BF * 2)             // 81920

__global__ __launch_bounds__(256, 2)
void k_gemm(int a2sel, int woff_l, int woff_r,
            const float* __restrict__ bias,
            float* __restrict__ Cext, int osel,   // 0=ext fp32, 1=h0, 2=h1
            int K, int relu) {
    extern __shared__ __nv_bfloat16 sm[];
    const uint32_t sb = smem_u32p(sm);

    const __nv_bfloat16* A2h = (a2sel == 0) ? g_xh : (a2sel == 1 ? g_h0h : g_h1h);
    const __nv_bfloat16* A2l = (a2sel == 0) ? g_xl : (a2sel == 1 ? g_h0l : g_h1l);

    const int tid  = threadIdx.x;
    const int wid  = tid >> 5;
    const int lane = tid & 31;
    const int wm   = wid & 3;
    const int wn   = wid >> 2;
    const int bm   = blockIdx.x * BM;
    const int bn   = blockIdx.y * BN;
    const int r4   = lane >> 2;
    const int c2   = (lane & 3) * 2;

    // ldmatrix per-lane row offset (bf16 units): lanes 0-15 -> rows, 16-31 -> rows @ k+8
    const int loff = (lane < 16) ? lane * SBF : (lane - 16) * SBF + 8;

    const int KCH = K / 32;
    const int NCH = 2 * KCH;

    float acc[2][8][4];
#pragma unroll
    for (int mt = 0; mt < 2; mt++)
#pragma unroll
        for (int nt = 0; nt < 8; nt++)
#pragma unroll
            for (int q = 0; q < 4; q++) acc[mt][nt][q] = 0.0f;

    auto issue = [&](int c) {
        int part = (c >= KCH) ? 1 : 0;
        int k0 = (c - part * KCH) * 32;
        const __nv_bfloat16* Ah = part ? A2h : g_aggh;
        const __nv_bfloat16* Al = part ? A2l : g_aggl;
        const __nv_bfloat16* Bh = g_Wh + (part ? woff_r : woff_l);
        const __nv_bfloat16* Bl = g_Wl + (part ? woff_r : woff_l);
        uint32_t st = sb + (c & 1) * (STG_BF * 2);
#pragma unroll
        for (int it = 0; it < 2; ++it) {
            int f = tid + 256 * it;
            int row = f >> 2, q = f & 3;
            int rg = bm + row;
            size_t go = (size_t)rg * K + k0 + q * 8;
            uint32_t so = row * (SBF * 2) + q * 16;
            int sz = (rg < NN) ? 16 : 0;
            cpa16(st + so, Ah + go, sz);
            cpa16(st + TILE_BF * 2 + so, Al + go, sz);
        }
#pragma unroll
        for (int it = 0; it < 2; ++it) {
            int f = tid + 256 * it;
            int n = f >> 2, q = f & 3;
            size_t go = (size_t)(bn + n) * K + k0 + q * 8;
            uint32_t so = n * (SBF * 2) + q * 16;
            cpa16(st + 2 * TILE_BF * 2 + so, Bh + go, 16);
            cpa16(st + 3 * TILE_BF * 2 + so, Bl + go, 16);
        }
        asm volatile("cp.async.commit_group;" ::: "memory");
    };

    issue(0);
    if (NCH > 1) issue(1);

#pragma unroll 1
    for (int c = 0; c < NCH; ++c) {
        if (c + 1 < NCH)
            asm volatile("cp.async.wait_group 1;" ::: "memory");
        else
            asm volatile("cp.async.wait_group 0;" ::: "memory");
        __syncthreads();

        uint32_t st = sb + (c & 1) * (STG_BF * 2);
        uint32_t aH = st;
        uint32_t aL = st + TILE_BF * 2;
        uint32_t bH = st + 2 * TILE_BF * 2;
        uint32_t bL = st + 3 * TILE_BF * 2;

#pragma unroll
        for (int kk = 0; kk < 32; kk += 16) {
            uint32_t ah[2][4], al[2][4];
#pragma unroll
            for (int mt = 0; mt < 2; ++mt) {
                uint32_t base = ((wm * 32 + mt * 16) * SBF + kk + loff) * 2;
                ldsm4(ah[mt], aH + base);
                ldsm4(al[mt], aL + base);
            }
#pragma unroll
            for (int p = 0; p < 4; ++p) {
                uint32_t nb = ((wn * 64 + p * 16) * SBF + kk + loff) * 2;
                uint32_t bh[4], bl[4];
                ldsm4(bh, bH + nb);
                ldsm4(bl, bL + nb);
                // bh = { b0(nt=2p), b0(2p+1), b1(2p), b1(2p+1) }
#pragma unroll
                for (int mt = 0; mt < 2; ++mt) {
                    mma2(acc[mt][2 * p + 0], ah[mt], bh[0], bh[2]);
                    mma2(acc[mt][2 * p + 0], al[mt], bh[0], bh[2]);
                    mma2(acc[mt][2 * p + 0], ah[mt], bl[0], bl[2]);
                    mma2(acc[mt][2 * p + 1], ah[mt], bh[1], bh[3]);
                    mma2(acc[mt][2 * p + 1], al[mt], bh[1], bh[3]);
                    mma2(acc[mt][2 * p + 1], ah[mt], bl[1], bl[3]);
                }
            }
        }
        __syncthreads();
        if (c + 2 < NCH) issue(c + 2);
    }

    // ---- epilogue ----
    __nv_bfloat16* Ch = (osel == 1) ? g_h0h : g_h1h;
    __nv_bfloat16* Cl = (osel == 1) ? g_h0l : g_h1l;
#pragma unroll
    for (int nt = 0; nt < 8; ++nt) {
        int col = bn + wn * 64 + nt * 8 + c2;
        float2 bv = *reinterpret_cast<const float2*>(bias + col);
#pragma unroll
        for (int mt = 0; mt < 2; ++mt) {
            int row0 = bm + wm * 32 + mt * 16 + r4;
            float2 o0, o1;
            o0.x = acc[mt][nt][0] + bv.x;
            o0.y = acc[mt][nt][1] + bv.y;
            o1.x = acc[mt][nt][2] + bv.x;
            o1.y = acc[mt][nt][3] + bv.y;
            if (relu) {
                o0.x = fmaxf(o0.x, 0.f); o0.y = fmaxf(o0.y, 0.f);
                o1.x = fmaxf(o1.x, 0.f); o1.y = fmaxf(o1.y, 0.f);
            }
            if (osel == 0) {
                if (row0 < NN)
                    *reinterpret_cast<float2*>(Cext + (size_t)row0 * 256 + col) = o0;
                if (row0 + 8 < NN)
                    *reinterpret_cast<float2*>(Cext + (size_t)(row0 + 8) * 256 + col) = o1;
            } else {
                if (row0 < NN) {
                    __nv_bfloat16 ha, la, hb, lb;
                    split_bf16(o0.x, ha, la);
                    split_bf16(o0.y, hb, lb);
                    *reinterpret_cast<uint32_t*>(Ch + (size_t)row0 * 256 + col) = pack2(ha, hb);
                    *reinterpret_cast<uint32_t*>(Cl + (size_t)row0 * 256 + col) = pack2(la, lb);
                }
                if (row0 + 8 < NN) {
                    __nv_bfloat16 ha, la, hb, lb;
                    split_bf16(o1.x, ha, la);
                    split_bf16(o1.y, hb, lb);
                    *reinterpret_cast<uint32_t*>(Ch + (size_t)(row0 + 8) * 256 + col) = pack2(ha, hb);
                    *reinterpret_cast<uint32_t*>(Cl + (size_t)(row0 + 8) * 256 + col) = pack2(la, lb);
                }
            }
        }
    }
}

// ---------------------------------------------------------------------------
// launch (single stream, serial fused schedule)
// ---------------------------------------------------------------------------
extern "C" void kernel_launch(void* const* d_in, const int* in_sizes, int n_in,
                              void* d_out, int out_size) {
    const float* x    = (const float*)d_in[0];
    const float* W_l0 = (const float*)d_in[1];
    const float* b_l0 = (const float*)d_in[2];
    const float* W_r0 = (const float*)d_in[3];
    const float* W_l1 = (const float*)d_in[4];
    const float* b_l1 = (const float*)d_in[5];
    const float* W_r1 = (const float*)d_in[6];
    const float* W_l2 = (const float*)d_in[7];
    const float* b_l2 = (const float*)d_in[8];
    const float* W_r2 = (const float*)d_in[9];
    const int*   src  = (const int*)d_in[10];
    const int*   dst  = (const int*)d_in[11];
    float*       out  = (float*)d_out;

    const int T = 256;
    dim3 gg((NN + BM - 1) / BM, 256 / BN);

    cudaFuncSetAttribute(k_gemm, cudaFuncAttributeMaxDynamicSharedMemorySize, SMEM_BYTES);

    // ---- CSR build ----
    k_zero_cnt<<<(NN + T - 1) / T, T>>>();
    k_hist<<<(NE + T - 1) / T, T>>>(dst);
    k_scan1<<<NB1, SCAN_B>>>();
    k_scan2<<<1, 256>>>();
    k_scan3<<<(NN + T - 1) / T, T>>>();
    k_place<<<(NE + T - 1) / T, T>>>(src, dst);

    // ---- prep ----
    k_prep_x<<<(NN * 64 + T - 1) / T, T>>>(x);
    k_prep_w_all<<<(327680 + T - 1) / T, T>>>(W_l0, W_r0, W_l1, W_r1, W_l2, W_r2);

    // ---- layer 0 (K = 128) ----
    k_aggregate<128><<<(NN * 32 + T - 1) / T, T>>>(0);
    k_gemm<<<gg, T, SMEM_BYTES>>>(0, 0, 32768, b_l0, nullptr, 1, 128, 1);

    // ---- layer 1 (K = 256) ----
    k_aggregate<256><<<(NN * 2 * 32 + T - 1) / T, T>>>(1);
    k_gemm<<<gg, T, SMEM_BYTES>>>(1, 65536, 131072, b_l1, nullptr, 2, 256, 1);

    // ---- layer 2 (K = 256, no relu, write d_out) ----
    k_aggregate<256><<<(NN * 2 * 32 + T - 1) / T, T>>>(2);
    k_gemm<<<gg, T, SMEM_BYTES>>>(2, 196608, 262144, b_l2, out, 0, 256, 0);
}

// round 11
// speedup vs baseline: 1.1777x; 1.1777x over previous
#include <cuda_runtime.h>
#include <cuda_bf16.h>
#include <cstdint>

// ---------------------------------------------------------------------------
// 3-layer GraphSAGE (mean aggregation), fp32-grade via bf16 hi/lo pairs.
//   activations stored packed: u32 = (bf16_hi << 16) | bf16_lo, value = hi+lo
//   aggregation: CSR segment-mean gather (no float atomics), 8x unrolled
//   GEMM: mma.sync m16n8k16 bf16, 3 products (AhBh + AlBh + AhBl),
//         cp.async double-buffered pipeline, PRMT hi/lo extraction.
//   CSR build overlapped with x/weight prep on a second stream.
// N = 100000, E = 1600000, dims 128 -> 256 -> 256 -> 256.
// ---------------------------------------------------------------------------

#define NN 100000
#define NE 1600000
#define CMAX 256

// ---------------- packed activation buffers --------------------------------
__device__ uint32_t g_xp  [(size_t)NN * 128];
__device__ uint32_t g_aggp[(size_t)NN * CMAX];
__device__ uint32_t g_h0p [(size_t)NN * CMAX];
__device__ uint32_t g_h1p [(size_t)NN * CMAX];

// packed transposed weights [N=256, K] (K contiguous)
// offsets: l0:0(K=128) r0:32768  l1:65536 r1:131072 l2:196608 r2:262144
#define WBUF_TOTAL (2 * 128 * 256 + 4 * 256 * 256)
__device__ uint32_t g_Wp[WBUF_TOTAL];

// CSR build
#define SCAN_B 512
#define NB1 ((NN + SCAN_B - 1) / SCAN_B)
__device__ int g_cnt[NN];
__device__ int g_pos[NN];
__device__ int g_rowptr[NN];
__device__ int g_srcs[NE];
__device__ int g_scan[NN];
__device__ int g_part[NB1];
__device__ int g_partscan[NB1];

// ---------------------------------------------------------------------------
// helpers
// ---------------------------------------------------------------------------
__device__ __forceinline__ uint32_t pack_split(float v) {
    __nv_bfloat16 h = __float2bfloat16_rn(v);
    float r = v - __bfloat162float(h);
    __nv_bfloat16 l = __float2bfloat16_rn(r);
    return ((uint32_t)__bfloat16_as_ushort(h) << 16) | (uint32_t)__bfloat16_as_ushort(l);
}
__device__ __forceinline__ float unpack_val(uint32_t p) {
    return __uint_as_float(p & 0xFFFF0000u) + __uint_as_float(p << 16);
}
__device__ __forceinline__ void cpa16(uint32_t saddr, const void* g, int sz) {
    asm volatile("cp.async.ca.shared.global [%0], [%1], 16, %2;"
                 :: "r"(saddr), "l"(g), "r"(sz) : "memory");
}
__device__ __forceinline__ uint32_t smem_u32p(const void* p) {
    uint32_t a;
    asm("{ .reg .u64 t; cvta.to.shared.u64 t, %1; cvt.u32.u64 %0, t; }" : "=r"(a) : "l"(p));
    return a;
}
__device__ __forceinline__ void mma_bf16(float* c, const uint32_t* a, const uint32_t* b) {
    asm volatile(
        "mma.sync.aligned.m16n8k16.row.col.f32.bf16.bf16.f32 "
        "{%0,%1,%2,%3}, {%4,%5,%6,%7}, {%8,%9}, {%0,%1,%2,%3};"
        : "+f"(c[0]), "+f"(c[1]), "+f"(c[2]), "+f"(c[3])
        : "r"(a[0]), "r"(a[1]), "r"(a[2]), "r"(a[3]), "r"(b[0]), "r"(b[1]));
}

// ---------------------------------------------------------------------------
// CSR build kernels
// ---------------------------------------------------------------------------
__global__ void k_zero_cnt() {
    int i = blockIdx.x * blockDim.x + threadIdx.x;
    if (i < NN) { g_cnt[i] = 0; g_pos[i] = 0; }
}
__global__ void k_hist(const int* __restrict__ dst) {
    int i = blockIdx.x * blockDim.x + threadIdx.x;
    if (i < NE) atomicAdd(&g_cnt[dst[i]], 1);
}
__global__ void k_scan1() {
    __shared__ int s[SCAN_B];
    int t = threadIdx.x;
    int idx = blockIdx.x * SCAN_B + t;
    int v = (idx < NN) ? g_cnt[idx] : 0;
    s[t] = v;
    __syncthreads();
#pragma unroll
    for (int off = 1; off < SCAN_B; off <<= 1) {
        int tmp = (t >= off) ? s[t - off] : 0;
        __syncthreads();
        s[t] += tmp;
        __syncthreads();
    }
    if (idx < NN) g_scan[idx] = s[t];
    if (t == SCAN_B - 1) g_part[blockIdx.x] = s[t];
}
__global__ void k_scan2() {
    __shared__ int s[256];
    int t = threadIdx.x;
    int v = (t < NB1) ? g_part[t] : 0;
    s[t] = v;
    __syncthreads();
#pragma unroll
    for (int off = 1; off < 256; off <<= 1) {
        int tmp = (t >= off) ? s[t - off] : 0;
        __syncthreads();
        s[t] += tmp;
        __syncthreads();
    }
    if (t < NB1) g_partscan[t] = s[t];
}
__global__ void k_scan3() {
    int idx = blockIdx.x * blockDim.x + threadIdx.x;
    if (idx < NN) {
        int b = idx / SCAN_B;
        int boff = (b > 0) ? g_partscan[b - 1] : 0;
        g_rowptr[idx] = g_scan[idx] - g_cnt[idx] + boff;
    }
}
__global__ void k_place(const int* __restrict__ src, const int* __restrict__ dst) {
    int i = blockIdx.x * blockDim.x + threadIdx.x;
    if (i < NE) {
        int d = dst[i];
        int pos = g_rowptr[d] + atomicAdd(&g_pos[d], 1);
        g_srcs[pos] = src[i];
    }
}

// ---------------------------------------------------------------------------
// prep: pack x; pack+transpose all 6 weights in ONE kernel
// ---------------------------------------------------------------------------
__global__ void k_prep_x(const float* __restrict__ x) {
    int i = blockIdx.x * blockDim.x + threadIdx.x;
    if (i < NN * 128) g_xp[i] = pack_split(x[i]);
}
__global__ void k_prep_w_all(const float* __restrict__ Wl0, const float* __restrict__ Wr0,
                             const float* __restrict__ Wl1, const float* __restrict__ Wr1,
                             const float* __restrict__ Wl2, const float* __restrict__ Wr2) {
    int i = blockIdx.x * blockDim.x + threadIdx.x;
    if (i >= WBUF_TOTAL) return;
    const float* W;
    int base, K, li;
    if (i < 65536) {
        K = 128;
        if (i < 32768) { W = Wl0; base = 0; li = i; }
        else           { W = Wr0; base = 32768; li = i - 32768; }
    } else {
        K = 256;
        int j = i - 65536;
        int seg = j >> 16;
        li = j & 65535;
        base = 65536 + (seg << 16);
        W = (seg == 0) ? Wl1 : (seg == 1) ? Wr1 : (seg == 2) ? Wl2 : Wr2;
    }
    int k = li >> 8;
    int n = li & 255;
    g_Wp[base + n * K + k] = pack_split(W[li]);
}

// ---------------------------------------------------------------------------
// aggregation: segment-mean gather over packed values. one warp per
// (node, 128-ch chunk); lanes hold 4 channels each (uint4 of packed u32).
// 8x unrolled for MLP.
// ---------------------------------------------------------------------------
__device__ __forceinline__ void acc_packed(float4& a, uint4 v) {
    a.x += unpack_val(v.x);
    a.y += unpack_val(v.y);
    a.z += unpack_val(v.z);
    a.w += unpack_val(v.w);
}

template <int CHUNKS>
__global__ void k_aggregate(int xsel) {
    const uint32_t* x = (xsel == 0) ? g_xp : (xsel == 1 ? g_h0p : g_h1p);
    const int CV = CHUNKS * 32;   // uint4 per row
    int gw = (blockIdx.x * blockDim.x + threadIdx.x) >> 5;
    int lane = threadIdx.x & 31;
    int node = gw / CHUNKS;
    int chunk = gw - node * CHUNKS;
    if (node >= NN) return;

    int beg = g_rowptr[node];
    int len = g_cnt[node];
    int end = beg + len;
    size_t coff = (size_t)chunk * 32 + lane;
    const uint4* xv = reinterpret_cast<const uint4*>(x);
    float4 acc = make_float4(0.f, 0.f, 0.f, 0.f);

    int j = beg;
    for (; j + 8 <= end; j += 8) {
        int s0 = __ldg(&g_srcs[j + 0]);
        int s1 = __ldg(&g_srcs[j + 1]);
        int s2 = __ldg(&g_srcs[j + 2]);
        int s3 = __ldg(&g_srcs[j + 3]);
        int s4 = __ldg(&g_srcs[j + 4]);
        int s5 = __ldg(&g_srcs[j + 5]);
        int s6 = __ldg(&g_srcs[j + 6]);
        int s7 = __ldg(&g_srcs[j + 7]);
        uint4 v0 = xv[(size_t)s0 * CV + coff];
        uint4 v1 = xv[(size_t)s1 * CV + coff];
        uint4 v2 = xv[(size_t)s2 * CV + coff];
        uint4 v3 = xv[(size_t)s3 * CV + coff];
        uint4 v4 = xv[(size_t)s4 * CV + coff];
        uint4 v5 = xv[(size_t)s5 * CV + coff];
        uint4 v6 = xv[(size_t)s6 * CV + coff];
        uint4 v7 = xv[(size_t)s7 * CV + coff];
        acc_packed(acc, v0); acc_packed(acc, v1);
        acc_packed(acc, v2); acc_packed(acc, v3);
        acc_packed(acc, v4); acc_packed(acc, v5);
        acc_packed(acc, v6); acc_packed(acc, v7);
    }
    for (; j + 2 <= end; j += 2) {
        int s0 = __ldg(&g_srcs[j + 0]);
        int s1 = __ldg(&g_srcs[j + 1]);
        uint4 v0 = xv[(size_t)s0 * CV + coff];
        uint4 v1 = xv[(size_t)s1 * CV + coff];
        acc_packed(acc, v0); acc_packed(acc, v1);
    }
    for (; j < end; ++j) {
        int s = __ldg(&g_srcs[j]);
        acc_packed(acc, xv[(size_t)s * CV + coff]);
    }
    float inv = 1.0f / fmaxf((float)len, 1.0f);
    uint4 o;
    o.x = pack_split(acc.x * inv);
    o.y = pack_split(acc.y * inv);
    o.z = pack_split(acc.z * inv);
    o.w = pack_split(acc.w * inv);
    reinterpret_cast<uint4*>(g_aggp)[(size_t)node * CV + coff] = o;
}

// ---------------------------------------------------------------------------
// fused dual-GEMM: C = agg@W_l + A2@W_r + bias (+relu)
//   packed smem, cp.async 2-stage pipeline, PRMT hi/lo extraction,
//   3 mma products per tile.  (R6 structure — best measured)
// ---------------------------------------------------------------------------
#define BM 128
#define BN 128
#define S40 40                      // u32 stride per smem row (32 data + 8 pad)
#define ASZ (128 * S40)             // 5120 u32 per stage array
#define STGU (2 * ASZ)              // A + B per stage (u32)
#define SMEM_BYTES (2 * STGU * 4)   // 81920

__global__ __launch_bounds__(256, 2)
void k_gemm_mma(int a2sel, int woff_l, int woff_r,
                const float* __restrict__ bias,
                float* __restrict__ Cext, int csel,
                int K, int relu) {
    extern __shared__ uint32_t smem[];
    const uint32_t sb = smem_u32p(smem);

    const uint32_t* A2 = (a2sel == 0) ? g_xp : (a2sel == 1 ? g_h0p : g_h1p);
    const int tid  = threadIdx.x;
    const int wid  = tid >> 5;
    const int lane = tid & 31;
    const int wm   = wid & 3;
    const int wn   = wid >> 2;
    const int bm   = blockIdx.x * BM;
    const int bn   = blockIdx.y * BN;
    const int r4   = lane >> 2;
    const int c2   = (lane & 3) * 2;

    const int KCH = K / 32;
    const int NCH = 2 * KCH;

    float acc[2][8][4];
#pragma unroll
    for (int mt = 0; mt < 2; mt++)
#pragma unroll
        for (int nt = 0; nt < 8; nt++)
#pragma unroll
            for (int q = 0; q < 4; q++) acc[mt][nt][q] = 0.0f;

    auto issue = [&](int c) {
        int part = (c >= KCH) ? 1 : 0;
        int k0 = (c - part * KCH) * 32;
        const uint32_t* Abase = part ? A2 : g_aggp;
        int woff = part ? woff_r : woff_l;
        int buf = c & 1;
        uint32_t sA = sb + (buf * STGU) * 4;
        uint32_t sB = sA + ASZ * 4;
#pragma unroll
        for (int i = 0; i < 4; ++i) {
            int f = tid + 256 * i;
            int row = f >> 3, c4 = f & 7;
            int rg = bm + row;
            const uint32_t* src = Abase + (size_t)rg * K + k0 + c4 * 4;
            cpa16(sA + (row * S40 + c4 * 4) * 4, src, (rg < NN) ? 16 : 0);
        }
#pragma unroll
        for (int i = 0; i < 4; ++i) {
            int f = tid + 256 * i;
            int n = f >> 3, c4 = f & 7;
            const uint32_t* src = g_Wp + woff + (size_t)(bn + n) * K + k0 + c4 * 4;
            cpa16(sB + (n * S40 + c4 * 4) * 4, src, 16);
        }
        asm volatile("cp.async.commit_group;" ::: "memory");
    };

    issue(0);
    if (NCH > 1) issue(1);

#pragma unroll 1
    for (int c = 0; c < NCH; ++c) {
        if (c + 1 < NCH)
            asm volatile("cp.async.wait_group 1;" ::: "memory");
        else
            asm volatile("cp.async.wait_group 0;" ::: "memory");
        __syncthreads();

        const uint32_t* sA = smem + (c & 1) * STGU;
        const uint32_t* sB = sA + ASZ;

#pragma unroll
        for (int kk = 0; kk < 32; kk += 16) {
            uint32_t ah[2][4], al[2][4];
#pragma unroll
            for (int mt = 0; mt < 2; ++mt) {
                int rb = (wm * 32 + mt * 16 + r4) * S40 + kk + c2;
                uint2 q0 = *reinterpret_cast<const uint2*>(&sA[rb]);
                uint2 q1 = *reinterpret_cast<const uint2*>(&sA[rb + 8 * S40]);
                uint2 q2 = *reinterpret_cast<const uint2*>(&sA[rb + 8]);
                uint2 q3 = *reinterpret_cast<const uint2*>(&sA[rb + 8 * S40 + 8]);
                ah[mt][0] = __byte_perm(q0.x, q0.y, 0x7632);
                al[mt][0] = __byte_perm(q0.x, q0.y, 0x5410);
                ah[mt][1] = __byte_perm(q1.x, q1.y, 0x7632);
                al[mt][1] = __byte_perm(q1.x, q1.y, 0x5410);
                ah[mt][2] = __byte_perm(q2.x, q2.y, 0x7632);
                al[mt][2] = __byte_perm(q2.x, q2.y, 0x5410);
                ah[mt][3] = __byte_perm(q3.x, q3.y, 0x7632);
                al[mt][3] = __byte_perm(q3.x, q3.y, 0x5410);
            }
#pragma unroll
            for (int nt = 0; nt < 8; ++nt) {
                int nb = (wn * 64 + nt * 8 + r4) * S40 + kk + c2;
                uint2 q0 = *reinterpret_cast<const uint2*>(&sB[nb]);
                uint2 q1 = *reinterpret_cast<const uint2*>(&sB[nb + 8]);
                uint32_t bh[2], bl[2];
                bh[0] = __byte_perm(q0.x, q0.y, 0x7632);
                bl[0] = __byte_perm(q0.x, q0.y, 0x5410);
                bh[1] = __byte_perm(q1.x, q1.y, 0x7632);
                bl[1] = __byte_perm(q1.x, q1.y, 0x5410);
#pragma unroll
                for (int mt = 0; mt < 2; ++mt) {
                    mma_bf16(acc[mt][nt], ah[mt], bh);
                    mma_bf16(acc[mt][nt], al[mt], bh);
                    mma_bf16(acc[mt][nt], ah[mt], bl);
                }
            }
        }
        __syncthreads();
        if (c + 2 < NCH) issue(c + 2);
    }

    // ---- epilogue ----
    uint32_t* Cp = (csel == 1) ? g_h0p : g_h1p;
#pragma unroll
    for (int nt = 0; nt < 8; ++nt) {
        int col = bn + wn * 64 + nt * 8 + c2;
        float2 bv = *reinterpret_cast<const float2*>(bias + col);
#pragma unroll
        for (int mt = 0; mt < 2; ++mt) {
            int row0 = bm + wm * 32 + mt * 16 + r4;
            float2 o0, o1;
            o0.x = acc[mt][nt][0] + bv.x;
            o0.y = acc[mt][nt][1] + bv.y;
            o1.x = acc[mt][nt][2] + bv.x;
            o1.y = acc[mt][nt][3] + bv.y;
            if (relu) {
                o0.x = fmaxf(o0.x, 0.f); o0.y = fmaxf(o0.y, 0.f);
                o1.x = fmaxf(o1.x, 0.f); o1.y = fmaxf(o1.y, 0.f);
            }
            if (csel == 0) {
                if (row0 < NN)
                    *reinterpret_cast<float2*>(Cext + (size_t)row0 * 256 + col) = o0;
                if (row0 + 8 < NN)
                    *reinterpret_cast<float2*>(Cext + (size_t)(row0 + 8) * 256 + col) = o1;
            } else {
                if (row0 < NN) {
                    uint2 p = make_uint2(pack_split(o0.x), pack_split(o0.y));
                    *reinterpret_cast<uint2*>(Cp + (size_t)row0 * 256 + col) = p;
                }
                if (row0 + 8 < NN) {
                    uint2 p = make_uint2(pack_split(o1.x), pack_split(o1.y));
                    *reinterpret_cast<uint2*>(Cp + (size_t)(row0 + 8) * 256 + col) = p;
                }
            }
        }
    }
}

// ---------------------------------------------------------------------------
// launch: CSR build (stream B) overlapped with prep (stream A); then the
// serial fused per-layer schedule on stream A.
// ---------------------------------------------------------------------------
extern "C" void kernel_launch(void* const* d_in, const int* in_sizes, int n_in,
                              void* d_out, int out_size) {
    const float* x    = (const float*)d_in[0];
    const float* W_l0 = (const float*)d_in[1];
    const float* b_l0 = (const float*)d_in[2];
    const float* W_r0 = (const float*)d_in[3];
    const float* W_l1 = (const float*)d_in[4];
    const float* b_l1 = (const float*)d_in[5];
    const float* W_r1 = (const float*)d_in[6];
    const float* W_l2 = (const float*)d_in[7];
    const float* b_l2 = (const float*)d_in[8];
    const float* W_r2 = (const float*)d_in[9];
    const int*   src  = (const int*)d_in[10];
    const int*   dst  = (const int*)d_in[11];
    float*       out  = (float*)d_out;

    const int T = 256;
    dim3 gg((NN + BM - 1) / BM, 256 / BN);

    static cudaStream_t sB = nullptr;
    static cudaEvent_t evFork, evCSR;
    if (!sB) {
        cudaStreamCreateWithFlags(&sB, cudaStreamNonBlocking);
        cudaEventCreateWithFlags(&evFork, cudaEventDisableTiming);
        cudaEventCreateWithFlags(&evCSR, cudaEventDisableTiming);
        cudaFuncSetAttribute(k_gemm_mma, cudaFuncAttributeMaxDynamicSharedMemorySize,
                             SMEM_BYTES);
    }

    // ---- fork: CSR build on stream B ----
    cudaEventRecord(evFork, 0);
    cudaStreamWaitEvent(sB, evFork, 0);
    k_zero_cnt<<<(NN + T - 1) / T, T, 0, sB>>>();
    k_hist<<<(NE + T - 1) / T, T, 0, sB>>>(dst);
    k_scan1<<<NB1, SCAN_B, 0, sB>>>();
    k_scan2<<<1, 256, 0, sB>>>();
    k_scan3<<<(NN + T - 1) / T, T, 0, sB>>>();
    k_place<<<(NE + T - 1) / T, T, 0, sB>>>(src, dst);
    cudaEventRecord(evCSR, sB);

    // ---- prep on stream A (overlaps CSR) ----
    k_prep_x<<<(NN * 128 + T - 1) / T, T>>>(x);
    k_prep_w_all<<<(WBUF_TOTAL + T - 1) / T, T>>>(W_l0, W_r0, W_l1, W_r1, W_l2, W_r2);

    // ---- join ----
    cudaStreamWaitEvent(0, evCSR, 0);

    // ---- layer 0 (K = 128) ----
    k_aggregate<1><<<(NN * 32 + T - 1) / T, T>>>(0);
    k_gemm_mma<<<gg, T, SMEM_BYTES>>>(0, 0, 32768, b_l0, nullptr, 1, 128, 1);

    // ---- layer 1 (K = 256) ----
    k_aggregate<2><<<(NN * 2 * 32 + T - 1) / T, T>>>(1);
    k_gemm_mma<<<gg, T, SMEM_BYTES>>>(1, 65536, 131072, b_l1, nullptr, 2, 256, 1);

    // ---- layer 2 (K = 256, no relu, write d_out) ----
    k_aggregate<2><<<(NN * 2 * 32 + T - 1) / T, T>>>(2);
    k_gemm_mma<<<gg, T, SMEM_BYTES>>>(2, 196608, 262144, b_l2, out, 0, 256, 0);
}